// round 3
// baseline (speedup 1.0000x reference)
#include <cuda_runtime.h>
#include <cstdint>

#define MDIM   12288
#define CIN    8
#define NPAIR  4
#define COUT   16
#define KTAP   5

#define JS     128                 // columns per pipeline stage
#define NS     6                   // pipeline depth
#define NT     (MDIM / JS)         // 96 stages
#define RPW    8                   // rows per compute warp
#define NWC    4                   // compute warps
#define RPB    (RPW * NWC)         // 32 rows per CTA
#define NBLOCKS (MDIM / RPB)       // 384
#define NCT    (NWC * 32)          // 128 compute threads
#define NTHREADS (NCT + 32)        // +1 producer warp

#define LSTAGE_BYTES (RPB * JS * 4)    // 16384
#define PBUF_BYTES   (JS * CIN * 4)    // 4096

#define SM_FULL   0
#define SM_EMPTY  64
#define SM_PBUF   1024
#define SM_LBUF   (SM_PBUF + 2 * PBUF_BYTES)          // 9216
#define SMEM_TOTAL (SM_LBUF + NS * LSTAGE_BYTES)      // 107520

#define SWZ(b) ((b) ^ (((b) >> 3) & 0x70))

__device__ __align__(16) float g_pan[KTAP - 1][CIN * MDIM];

// ---------- small PTX helpers ----------
__device__ __forceinline__ uint32_t smem_u32(const void* p) {
    uint32_t a;
    asm("{ .reg .u64 t; cvta.to.shared.u64 t, %1; cvt.u32.u64 %0, t; }" : "=r"(a) : "l"(p));
    return a;
}
__device__ __forceinline__ unsigned long long pack2(float lo, float hi) {
    unsigned long long r;
    asm("mov.b64 %0, {%1, %2};" : "=l"(r) : "f"(lo), "f"(hi));
    return r;
}
__device__ __forceinline__ void unpack2(unsigned long long v, float& lo, float& hi) {
    asm("mov.b64 {%0, %1}, %2;" : "=f"(lo), "=f"(hi) : "l"(v));
}
__device__ __forceinline__ void fma2(unsigned long long& acc,
                                     unsigned long long a, unsigned long long b) {
    asm("fma.rn.f32x2 %0, %1, %2, %0;" : "+l"(acc) : "l"(a), "l"(b));
}
__device__ __forceinline__ void mbar_init(uint32_t a, uint32_t cnt) {
    asm volatile("mbarrier.init.shared.b64 [%0], %1;" :: "r"(a), "r"(cnt) : "memory");
}
__device__ __forceinline__ void mbar_expect_tx(uint32_t a, uint32_t bytes) {
    asm volatile("mbarrier.arrive.expect_tx.shared.b64 _, [%0], %1;" :: "r"(a), "r"(bytes) : "memory");
}
__device__ __forceinline__ void mbar_arrive(uint32_t a) {
    asm volatile("mbarrier.arrive.shared.b64 _, [%0];" :: "r"(a) : "memory");
}
__device__ __forceinline__ void mbar_wait_acq(uint32_t a, uint32_t ph) {
    asm volatile(
        "{\n\t.reg .pred P;\n\t"
        "WL%=:\n\t"
        "mbarrier.try_wait.parity.acquire.cta.shared::cta.b64 P, [%0], %1, 0x989680;\n\t"
        "@P bra.uni WD%=;\n\t"
        "bra.uni WL%=;\n\t"
        "WD%=:\n\t}"
        :: "r"(a), "r"(ph) : "memory");
}
__device__ __forceinline__ void mbar_wait_rlx(uint32_t a, uint32_t ph) {
    asm volatile(
        "{\n\t.reg .pred P;\n\t"
        "WL%=:\n\t"
        "mbarrier.try_wait.parity.relaxed.cta.shared::cta.b64 P, [%0], %1, 0x989680;\n\t"
        "@P bra.uni WD%=;\n\t"
        "bra.uni WL%=;\n\t"
        "WD%=:\n\t}"
        :: "r"(a), "r"(ph) : "memory");
}
__device__ __forceinline__ void bulk_g2s(uint32_t dst, const void* src, uint32_t bytes,
                                         uint32_t bar) {
    asm volatile(
        "cp.async.bulk.shared::cluster.global.mbarrier::complete_tx::bytes [%0], [%1], %2, [%3];"
        :: "r"(dst), "l"(src), "r"(bytes), "r"(bar) : "memory");
}
__device__ __forceinline__ void sts64(uint32_t a, unsigned long long v) {
    asm volatile("st.shared.b64 [%0], %1;" :: "r"(a), "l"(v) : "memory");
}

// next[i][m] = sum_j L[m][j] * cur[i][j]
__global__ __launch_bounds__(NTHREADS, 2)
void step_kernel(const float* __restrict__ L,
                 const float* __restrict__ cur,
                 float* __restrict__ nxt) {
    extern __shared__ __align__(1024) unsigned char dsm[];
    const uint32_t smb = smem_u32(dsm);
    const int tid = threadIdx.x;
    const int m0  = blockIdx.x * RPB;

    if (tid == 0) {
        for (int s = 0; s < NS; ++s) {
            mbar_init(smb + SM_FULL  + 8 * s, 1);
            mbar_init(smb + SM_EMPTY + 8 * s, NCT);
        }
    }
    __syncthreads();

    if (tid >= NCT) {
        // ---- producer warp: single thread issues bulk copies ----
        if (tid == NCT) {
            int ps = 0, pph = 1;
            for (int t = 0; t < NT; ++t) {
                mbar_wait_rlx(smb + SM_EMPTY + 8 * ps, pph);
                uint32_t fb = smb + SM_FULL + 8 * ps;
                mbar_expect_tx(fb, LSTAGE_BYTES);
                const float* src0 = L + (size_t)m0 * MDIM + t * JS;
                uint32_t dst0 = smb + SM_LBUF + ps * LSTAGE_BYTES;
#pragma unroll 4
                for (int r = 0; r < RPB; ++r)
                    bulk_g2s(dst0 + r * (JS * 4), src0 + (size_t)r * MDIM, JS * 4, fb);
                if (++ps == NS) { ps = 0; pph ^= 1; }
            }
        }
        return;
    }

    // ---- compute threads ----
    const int lane = tid & 31;
    const int w    = tid >> 5;
    const int r0   = w * RPW;

    unsigned long long acc[RPW][NPAIR];
#pragma unroll
    for (int r = 0; r < RPW; ++r)
#pragma unroll
        for (int p = 0; p < NPAIR; ++p) acc[r][p] = 0ull;

    // prefetch panel tile 0 (4 pair-words per thread)
    float pv0[4], pv1[4];
#pragma unroll
    for (int q = 0; q < 4; ++q) {
        int idx = q * NCT + tid;            // 0..511
        int j = idx & (JS - 1), p = idx >> 7;
        pv0[q] = cur[(size_t)(2 * p) * MDIM + j];
        pv1[q] = cur[(size_t)(2 * p + 1) * MDIM + j];
    }

    int cs = 0, cph = 0;
    for (int t = 0; t < NT; ++t) {
        // stage panel tile t from prefetch regs (swizzled pair-packed)
        const uint32_t pboff = SM_PBUF + (t & 1) * PBUF_BYTES;
#pragma unroll
        for (int q = 0; q < 4; ++q) {
            int idx = q * NCT + tid;
            int j = idx & (JS - 1), p = idx >> 7;
            sts64(smb + pboff + SWZ(j * 32 + p * 8), pack2(pv0[q], pv1[q]));
        }
        // prefetch panel tile t+1
        if (t + 1 < NT) {
            const int jb = (t + 1) * JS;
#pragma unroll
            for (int q = 0; q < 4; ++q) {
                int idx = q * NCT + tid;
                int j = idx & (JS - 1), p = idx >> 7;
                pv0[q] = cur[(size_t)(2 * p) * MDIM + jb + j];
                pv1[q] = cur[(size_t)(2 * p + 1) * MDIM + jb + j];
            }
        }
        asm volatile("bar.sync 1, %0;" :: "n"(NCT) : "memory");

        mbar_wait_acq(smb + SM_FULL + 8 * cs, (uint32_t)cph);

        const unsigned char* lb = dsm + SM_LBUF + cs * LSTAGE_BYTES;
        const unsigned char* pbp = dsm + pboff;

        float4 a[RPW];
#pragma unroll
        for (int r = 0; r < RPW; ++r)
            a[r] = *reinterpret_cast<const float4*>(lb + (r0 + r) * (JS * 4) + lane * 16);

#pragma unroll
        for (int jj = 0; jj < 4; ++jj) {
            const int jl = 4 * lane + jj;
            ulonglong2 q0 = *reinterpret_cast<const ulonglong2*>(pbp + SWZ(jl * 32));
            ulonglong2 q1 = *reinterpret_cast<const ulonglong2*>(pbp + SWZ(jl * 32 + 16));
#pragma unroll
            for (int r = 0; r < RPW; ++r) {
                float av = (jj == 0) ? a[r].x : (jj == 1) ? a[r].y
                         : (jj == 2) ? a[r].z : a[r].w;
                unsigned long long aa = pack2(av, av);
                fma2(acc[r][0], aa, q0.x);
                fma2(acc[r][1], aa, q0.y);
                fma2(acc[r][2], aa, q1.x);
                fma2(acc[r][3], aa, q1.y);
            }
        }
        mbar_arrive(smb + SM_EMPTY + 8 * cs);
        if (++cs == NS) { cs = 0; cph ^= 1; }
    }

    // warp reduction over lanes (disjoint j), then store
#pragma unroll
    for (int r = 0; r < RPW; ++r)
#pragma unroll
        for (int p = 0; p < NPAIR; ++p) {
            float v0, v1;
            unpack2(acc[r][p], v0, v1);
#pragma unroll
            for (int d = 16; d > 0; d >>= 1) {
                v0 += __shfl_down_sync(0xffffffffu, v0, d);
                v1 += __shfl_down_sync(0xffffffffu, v1, d);
            }
            if (lane == 0) {
                const int m = m0 + r0 + r;
                nxt[(size_t)(2 * p) * MDIM + m]     = v0;
                nxt[(size_t)(2 * p + 1) * MDIM + m] = v1;
            }
        }
}

// y[o][m] = bias[o] + sum_{i,k} theta[o][i][k] * P[k][i][m]
__global__ __launch_bounds__(256)
void mix_kernel(const float* __restrict__ x,
                const float* __restrict__ theta,
                const float* __restrict__ bias,
                float* __restrict__ out) {
    __shared__ float th[COUT * CIN * KTAP];
    __shared__ float bs[COUT];
    const int tid = threadIdx.x;
    for (int idx = tid; idx < COUT * CIN * KTAP; idx += blockDim.x)
        th[idx] = theta[idx];
    if (tid < COUT) bs[tid] = bias[tid];
    __syncthreads();

    const int m = blockIdx.x * blockDim.x + tid;
    if (m >= MDIM) return;

    float p[KTAP][CIN];
#pragma unroll
    for (int i = 0; i < CIN; ++i) p[0][i] = x[(size_t)i * MDIM + m];
#pragma unroll
    for (int k = 1; k < KTAP; ++k)
#pragma unroll
        for (int i = 0; i < CIN; ++i)
            p[k][i] = g_pan[k - 1][i * MDIM + m];

#pragma unroll
    for (int o = 0; o < COUT; ++o) {
        float s = bs[o];
#pragma unroll
        for (int i = 0; i < CIN; ++i)
#pragma unroll
            for (int k = 0; k < KTAP; ++k)
                s += th[(o * CIN + i) * KTAP + k] * p[k][i];
        out[(size_t)o * MDIM + m] = s;
    }
}

extern "C" void kernel_launch(void* const* d_in, const int* in_sizes, int n_in,
                              void* d_out, int out_size) {
    const float* L     = (const float*)d_in[0];
    const float* x     = (const float*)d_in[1];
    const float* theta = (const float*)d_in[2];
    const float* bias  = (const float*)d_in[3];
    float* out = (float*)d_out;

    static bool attr_set = false;
    if (!attr_set) {
        cudaFuncSetAttribute(step_kernel,
                             cudaFuncAttributeMaxDynamicSharedMemorySize, SMEM_TOTAL);
        attr_set = true;
    }

    float* pan = nullptr;
    cudaGetSymbolAddress((void**)&pan, g_pan);

    const size_t PSZ = (size_t)CIN * MDIM;

    step_kernel<<<NBLOCKS, NTHREADS, SMEM_TOTAL>>>(L, x,             pan + 0 * PSZ);
    step_kernel<<<NBLOCKS, NTHREADS, SMEM_TOTAL>>>(L, pan + 0 * PSZ, pan + 1 * PSZ);
    step_kernel<<<NBLOCKS, NTHREADS, SMEM_TOTAL>>>(L, pan + 1 * PSZ, pan + 2 * PSZ);
    step_kernel<<<NBLOCKS, NTHREADS, SMEM_TOTAL>>>(L, pan + 2 * PSZ, pan + 3 * PSZ);

    mix_kernel<<<(MDIM + 255) / 256, 256>>>(x, theta, bias, out);
}

// round 5
// speedup vs baseline: 1.2249x; 1.2249x over previous
#include <cuda_runtime.h>
#include <cstdint>

#define MDIM   12288
#define CIN    8
#define NPAIR  4
#define COUT   16
#define KTAP   5

#define JS     128                  // columns per pipeline stage
#define NS     6                    // stage ring depth
#define NINFL  (NS - 2)             // cp.async groups kept in flight
#define NT     (MDIM / JS)          // 96 stages
#define RPW    4                    // rows per warp
#define NW     8                    // warps per CTA
#define RPB    (RPW * NW)           // 32 rows per CTA
#define NBLOCKS (MDIM / RPB)        // 384
#define NTHREADS 256

#define LSTAGE  (RPB * JS * 4)      // 16384 B per L stage
#define PBUF    (JS * CIN * 4)      // 4096 B per panel tile
#define SM_PBUF 0
#define SM_LBUF (2 * PBUF)          // 8192
#define SMEM_TOTAL (SM_LBUF + NS * LSTAGE)   // 106496

#define SWZ(b) ((b) ^ (((b) >> 3) & 0x70))

__device__ __align__(16) float g_pan[KTAP - 1][CIN * MDIM];

// ---------- helpers ----------
__device__ __forceinline__ uint32_t smem_u32(const void* p) {
    uint32_t a;
    asm("{ .reg .u64 t; cvta.to.shared.u64 t, %1; cvt.u32.u64 %0, t; }" : "=r"(a) : "l"(p));
    return a;
}
__device__ __forceinline__ unsigned long long pack2(float lo, float hi) {
    unsigned long long r;
    asm("mov.b64 %0, {%1, %2};" : "=l"(r) : "f"(lo), "f"(hi));
    return r;
}
__device__ __forceinline__ void unpack2(unsigned long long v, float& lo, float& hi) {
    asm("mov.b64 {%0, %1}, %2;" : "=f"(lo), "=f"(hi) : "l"(v));
}
__device__ __forceinline__ void fma2(unsigned long long& acc,
                                     unsigned long long a, unsigned long long b) {
    asm("fma.rn.f32x2 %0, %1, %2, %0;" : "+l"(acc) : "l"(a), "l"(b));
}
__device__ __forceinline__ void cp16(uint32_t dst, const void* src) {
    asm volatile("cp.async.cg.shared.global [%0], [%1], 16;" :: "r"(dst), "l"(src) : "memory");
}
__device__ __forceinline__ void cp_commit() {
    asm volatile("cp.async.commit_group;" ::: "memory");
}
template <int N>
__device__ __forceinline__ void cp_wait() {
    asm volatile("cp.async.wait_group %0;" :: "n"(N) : "memory");
}
__device__ __forceinline__ void sts64(uint32_t a, unsigned long long v) {
    asm volatile("st.shared.b64 [%0], %1;" :: "r"(a), "l"(v) : "memory");
}

// next[i][m] = sum_j L[m][j] * cur[i][j]
__global__ __launch_bounds__(NTHREADS, 2)
void step_kernel(const float* __restrict__ L,
                 const float* __restrict__ cur,
                 float* __restrict__ nxt) {
    extern __shared__ __align__(1024) unsigned char dsm[];
    const uint32_t smb = smem_u32(dsm);
    const int tid  = threadIdx.x;
    const int lane = tid & 31;
    const int w    = tid >> 5;
    const int r0   = w * RPW;
    const int m0   = blockIdx.x * RPB;

    const float* Lbase = L + (size_t)m0 * MDIM;

    // ---- prologue: issue L stages 0..NS-2 ----
    // Stage layout: 32 rows x 512 B. 1024 float4 per stage; warp = one row.
#pragma unroll
    for (int t = 0; t < NS - 1; ++t) {
        uint32_t dst = smb + SM_LBUF + t * LSTAGE;
        const float* src = Lbase + t * JS;
#pragma unroll
        for (int q = 0; q < 4; ++q) {
            int c   = q * NTHREADS + tid;        // 0..1023
            int row = c >> 5;                    // 0..31
            int col = c & 31;                    // 0..31 float4 within row
            cp16(dst + row * (JS * 4) + col * 16,
                 src + (size_t)row * MDIM + col * 4);
        }
        cp_commit();
    }

    // panel prefetch for stage 0 (2 pair-words per thread)
    float pv0[2], pv1[2];
#pragma unroll
    for (int q = 0; q < 2; ++q) {
        int idx = q * NTHREADS + tid;            // 0..511
        int j = idx & (JS - 1), p = idx >> 7;    // p: 0..3
        pv0[q] = cur[(size_t)(2 * p) * MDIM + j];
        pv1[q] = cur[(size_t)(2 * p + 1) * MDIM + j];
    }

    unsigned long long acc[RPW][NPAIR];
#pragma unroll
    for (int r = 0; r < RPW; ++r)
#pragma unroll
        for (int p = 0; p < NPAIR; ++p) acc[r][p] = 0ull;

    for (int t = 0; t < NT; ++t) {
        cp_wait<NINFL>();                        // L stage t landed (this thread)

        // stage panel tile t (swizzled, pair-packed)
        const uint32_t pboff = SM_PBUF + (t & 1) * PBUF;
#pragma unroll
        for (int q = 0; q < 2; ++q) {
            int idx = q * NTHREADS + tid;
            int j = idx & (JS - 1), p = idx >> 7;
            sts64(smb + pboff + SWZ(j * 32 + p * 8), pack2(pv0[q], pv1[q]));
        }
        // prefetch panel tile t+1 (from L2-resident panel)
        if (t + 1 < NT) {
            const int jb = (t + 1) * JS;
#pragma unroll
            for (int q = 0; q < 2; ++q) {
                int idx = q * NTHREADS + tid;
                int j = idx & (JS - 1), p = idx >> 7;
                pv0[q] = cur[(size_t)(2 * p) * MDIM + jb + j];
                pv1[q] = cur[(size_t)(2 * p + 1) * MDIM + jb + j];
            }
        }

        __syncthreads();   // panel visible; all threads done with stage t-1's buffer

        // issue L stage t+NS-1 into the buffer freed by stage t-1
        if (t + NS - 1 < NT) {
            const int ts = t + NS - 1;
            uint32_t dst = smb + SM_LBUF + (ts % NS) * LSTAGE;
            const float* src = Lbase + ts * JS;
#pragma unroll
            for (int q = 0; q < 4; ++q) {
                int c   = q * NTHREADS + tid;
                int row = c >> 5;
                int col = c & 31;
                cp16(dst + row * (JS * 4) + col * 16,
                     src + (size_t)row * MDIM + col * 4);
            }
        }
        cp_commit();                             // always commit (tail keeps count exact)

        // ---- compute stage t ----
        const unsigned char* lb  = dsm + SM_LBUF + (t % NS) * LSTAGE;
        const unsigned char* pbp = dsm + pboff;

        float4 a[RPW];
#pragma unroll
        for (int r = 0; r < RPW; ++r)
            a[r] = *reinterpret_cast<const float4*>(lb + (r0 + r) * (JS * 4) + lane * 16);

#pragma unroll
        for (int jj = 0; jj < 4; ++jj) {
            const int jl = 4 * lane + jj;
            ulonglong2 q0 = *reinterpret_cast<const ulonglong2*>(pbp + SWZ(jl * 32));
            ulonglong2 q1 = *reinterpret_cast<const ulonglong2*>(pbp + SWZ(jl * 32 + 16));
#pragma unroll
            for (int r = 0; r < RPW; ++r) {
                float av = (jj == 0) ? a[r].x : (jj == 1) ? a[r].y
                         : (jj == 2) ? a[r].z : a[r].w;
                unsigned long long aa = pack2(av, av);
                fma2(acc[r][0], aa, q0.x);
                fma2(acc[r][1], aa, q0.y);
                fma2(acc[r][2], aa, q1.x);
                fma2(acc[r][3], aa, q1.y);
            }
        }
    }

    // warp reduction over lanes (disjoint j), then store
#pragma unroll
    for (int r = 0; r < RPW; ++r)
#pragma unroll
        for (int p = 0; p < NPAIR; ++p) {
            float v0, v1;
            unpack2(acc[r][p], v0, v1);
#pragma unroll
            for (int d = 16; d > 0; d >>= 1) {
                v0 += __shfl_down_sync(0xffffffffu, v0, d);
                v1 += __shfl_down_sync(0xffffffffu, v1, d);
            }
            if (lane == 0) {
                const int m = m0 + r0 + r;
                nxt[(size_t)(2 * p) * MDIM + m]     = v0;
                nxt[(size_t)(2 * p + 1) * MDIM + m] = v1;
            }
        }
}

// y[o][m] = bias[o] + sum_{i,k} theta[o][i][k] * P[k][i][m]
__global__ __launch_bounds__(256)
void mix_kernel(const float* __restrict__ x,
                const float* __restrict__ theta,
                const float* __restrict__ bias,
                float* __restrict__ out) {
    __shared__ float th[COUT * CIN * KTAP];
    __shared__ float bs[COUT];
    const int tid = threadIdx.x;
    for (int idx = tid; idx < COUT * CIN * KTAP; idx += blockDim.x)
        th[idx] = theta[idx];
    if (tid < COUT) bs[tid] = bias[tid];
    __syncthreads();

    const int m = blockIdx.x * blockDim.x + tid;
    if (m >= MDIM) return;

    float p[KTAP][CIN];
#pragma unroll
    for (int i = 0; i < CIN; ++i) p[0][i] = x[(size_t)i * MDIM + m];
#pragma unroll
    for (int k = 1; k < KTAP; ++k)
#pragma unroll
        for (int i = 0; i < CIN; ++i)
            p[k][i] = g_pan[k - 1][i * MDIM + m];

#pragma unroll
    for (int o = 0; o < COUT; ++o) {
        float s = bs[o];
#pragma unroll
        for (int i = 0; i < CIN; ++i)
#pragma unroll
            for (int k = 0; k < KTAP; ++k)
                s += th[(o * CIN + i) * KTAP + k] * p[k][i];
        out[(size_t)o * MDIM + m] = s;
    }
}

extern "C" void kernel_launch(void* const* d_in, const int* in_sizes, int n_in,
                              void* d_out, int out_size) {
    const float* L     = (const float*)d_in[0];
    const float* x     = (const float*)d_in[1];
    const float* theta = (const float*)d_in[2];
    const float* bias  = (const float*)d_in[3];
    float* out = (float*)d_out;

    cudaFuncSetAttribute(step_kernel,
                         cudaFuncAttributeMaxDynamicSharedMemorySize, SMEM_TOTAL);

    float* pan = nullptr;
    cudaGetSymbolAddress((void**)&pan, g_pan);

    const size_t PSZ = (size_t)CIN * MDIM;

    step_kernel<<<NBLOCKS, NTHREADS, SMEM_TOTAL>>>(L, x,             pan + 0 * PSZ);
    step_kernel<<<NBLOCKS, NTHREADS, SMEM_TOTAL>>>(L, pan + 0 * PSZ, pan + 1 * PSZ);
    step_kernel<<<NBLOCKS, NTHREADS, SMEM_TOTAL>>>(L, pan + 1 * PSZ, pan + 2 * PSZ);
    step_kernel<<<NBLOCKS, NTHREADS, SMEM_TOTAL>>>(L, pan + 2 * PSZ, pan + 3 * PSZ);

    mix_kernel<<<(MDIM + 255) / 256, 256>>>(x, theta, bias, out);
}

// round 6
// speedup vs baseline: 1.8912x; 1.5440x over previous
#include <cuda_runtime.h>
#include <cstdint>

#define MDIM 12288
#define CIN 8
#define NPAIR 4           // channel pairs (CIN/2)
#define COUT 16
#define KTAP 5
#define TJ 512            // j-tile staged in smem
#define RPW 4             // rows of L per warp
#define NW 8              // warps per block
#define RPB (RPW * NW)    // 32 rows per block
#define NBLOCKS (MDIM / RPB)  // 384

// 128B-row swizzle: XOR bits[7:10) into [4:7). Keeps >=8B alignment.
#define SWZ(b) ((b) ^ (((b) >> 3) & 0x70))

// Scratch panels for L^1 x .. L^4 x, each [CIN][MDIM].
__device__ __align__(16) float g_pan[KTAP - 1][CIN * MDIM];

__device__ __forceinline__ unsigned long long pack2(float lo, float hi) {
    unsigned long long r;
    asm("mov.b64 %0, {%1, %2};" : "=l"(r) : "f"(lo), "f"(hi));
    return r;
}
__device__ __forceinline__ void unpack2(unsigned long long v, float& lo, float& hi) {
    asm("mov.b64 {%0, %1}, %2;" : "=f"(lo), "=f"(hi) : "l"(v));
}
__device__ __forceinline__ void fma2(unsigned long long& acc,
                                     unsigned long long a, unsigned long long b) {
    asm("fma.rn.f32x2 %0, %1, %2, %0;" : "+l"(acc) : "l"(a), "l"(b));
}
__device__ __forceinline__ void l2_prefetch(const void* p) {
    asm volatile("prefetch.global.L2 [%0];" :: "l"(p));
}

// next[i][m] = sum_j L[m][j] * cur[i][j], channels packed in f32x2 pairs.
__global__ __launch_bounds__(256, 3)
void step_kernel(const float* __restrict__ L,
                 const float* __restrict__ cur,
                 float* __restrict__ nxt) {
    __shared__ __align__(16) unsigned char sp[TJ * NPAIR * 8];   // 16 KB

    const int tid  = threadIdx.x;
    const int lane = tid & 31;
    const int w    = tid >> 5;
    const int m0   = blockIdx.x * RPB + w * RPW;

    // Per-lane prefetch target: lane covers (row pr, 64B chunk pc) of the
    // 4-row x 512B block this warp will consume one j-tile ahead.
    const int pr = lane >> 3;          // 0..3
    const int pc = lane & 7;           // 0..7 (x64B)
    const float* pfbase = L + (size_t)(m0 + pr) * MDIM + pc * 16;

    unsigned long long acc[RPW][NPAIR];
#pragma unroll
    for (int r = 0; r < RPW; ++r)
#pragma unroll
        for (int p = 0; p < NPAIR; ++p) acc[r][p] = 0ull;

    const float4* cur4 = reinterpret_cast<const float4*>(cur);

    for (int jb = 0; jb < MDIM; jb += TJ) {
        // Stage panel tile as channel-pair interleaved, swizzled.
#pragma unroll
        for (int it = 0; it < (TJ * NPAIR) / 256; ++it) {      // 8 iters
            int idx = it * 256 + tid;
            int j   = idx & (TJ - 1);
            int p   = idx >> 9;                                 // 0..3
            unsigned long long v =
                pack2(cur[(size_t)(2 * p) * MDIM + jb + j],
                      cur[(size_t)(2 * p + 1) * MDIM + jb + j]);
            *reinterpret_cast<unsigned long long*>(sp + SWZ(j * 32 + p * 8)) = v;
        }
        __syncthreads();

        const bool do_pf = (jb + TJ) < MDIM;

#pragma unroll
        for (int s = 0; s < TJ / 128; ++s) {
            const int c = s * 32 + lane;                        // float4 index in tile
            float4 a[RPW];
#pragma unroll
            for (int r = 0; r < RPW; ++r)
                a[r] = __ldcs(reinterpret_cast<const float4*>(
                           L + (size_t)(m0 + r) * MDIM + jb) + c);

            // Prefetch the matching block one tile ahead (no regs, no scoreboard).
            if (do_pf)
                l2_prefetch(pfbase + jb + TJ + s * 128);

#pragma unroll
            for (int i = 0; i < CIN; ++i) {
                // i indexes channel pairs via q-words below
            }
#pragma unroll
            for (int jj = 0; jj < 4; ++jj) {
                const int jl = 4 * c + jj;                      // tile-local column
                ulonglong2 q0 = *reinterpret_cast<const ulonglong2*>(sp + SWZ(jl * 32));
                ulonglong2 q1 = *reinterpret_cast<const ulonglong2*>(sp + SWZ(jl * 32 + 16));
#pragma unroll
                for (int r = 0; r < RPW; ++r) {
                    float av = (jj == 0) ? a[r].x : (jj == 1) ? a[r].y
                             : (jj == 2) ? a[r].z : a[r].w;
                    unsigned long long aa = pack2(av, av);
                    fma2(acc[r][0], aa, q0.x);
                    fma2(acc[r][1], aa, q0.y);
                    fma2(acc[r][2], aa, q1.x);
                    fma2(acc[r][3], aa, q1.y);
                }
            }
        }
        __syncthreads();
    }

    // Warp reduction over lanes (disjoint j), then store.
#pragma unroll
    for (int r = 0; r < RPW; ++r)
#pragma unroll
        for (int p = 0; p < NPAIR; ++p) {
            float v0, v1;
            unpack2(acc[r][p], v0, v1);
#pragma unroll
            for (int d = 16; d > 0; d >>= 1) {
                v0 += __shfl_down_sync(0xffffffffu, v0, d);
                v1 += __shfl_down_sync(0xffffffffu, v1, d);
            }
            if (lane == 0) {
                nxt[(size_t)(2 * p) * MDIM + m0 + r]     = v0;
                nxt[(size_t)(2 * p + 1) * MDIM + m0 + r] = v1;
            }
        }
}

// y[o][m] = bias[o] + sum_{i,k} theta[o][i][k] * P[k][i][m]
__global__ __launch_bounds__(256)
void mix_kernel(const float* __restrict__ x,
                const float* __restrict__ theta,
                const float* __restrict__ bias,
                float* __restrict__ out) {
    __shared__ float th[COUT * CIN * KTAP];
    __shared__ float bs[COUT];
    const int tid = threadIdx.x;
    for (int idx = tid; idx < COUT * CIN * KTAP; idx += blockDim.x)
        th[idx] = theta[idx];
    if (tid < COUT) bs[tid] = bias[tid];
    __syncthreads();

    const int m = blockIdx.x * blockDim.x + tid;
    if (m >= MDIM) return;

    float p[KTAP][CIN];
#pragma unroll
    for (int i = 0; i < CIN; ++i) p[0][i] = x[(size_t)i * MDIM + m];
#pragma unroll
    for (int k = 1; k < KTAP; ++k)
#pragma unroll
        for (int i = 0; i < CIN; ++i)
            p[k][i] = g_pan[k - 1][i * MDIM + m];

#pragma unroll
    for (int o = 0; o < COUT; ++o) {
        float s = bs[o];
#pragma unroll
        for (int i = 0; i < CIN; ++i)
#pragma unroll
            for (int k = 0; k < KTAP; ++k)
                s += th[(o * CIN + i) * KTAP + k] * p[k][i];
        out[(size_t)o * MDIM + m] = s;
    }
}

extern "C" void kernel_launch(void* const* d_in, const int* in_sizes, int n_in,
                              void* d_out, int out_size) {
    const float* L     = (const float*)d_in[0];
    const float* x     = (const float*)d_in[1];
    const float* theta = (const float*)d_in[2];
    const float* bias  = (const float*)d_in[3];
    float* out = (float*)d_out;

    float* pan = nullptr;
    cudaGetSymbolAddress((void**)&pan, g_pan);

    const size_t PSZ = (size_t)CIN * MDIM;

    step_kernel<<<NBLOCKS, 256>>>(L, x,             pan + 0 * PSZ);
    step_kernel<<<NBLOCKS, 256>>>(L, pan + 0 * PSZ, pan + 1 * PSZ);
    step_kernel<<<NBLOCKS, 256>>>(L, pan + 1 * PSZ, pan + 2 * PSZ);
    step_kernel<<<NBLOCKS, 256>>>(L, pan + 2 * PSZ, pan + 3 * PSZ);

    mix_kernel<<<(MDIM + 255) / 256, 256>>>(x, theta, bias, out);
}